// round 8
// baseline (speedup 1.0000x reference)
#include <cuda_runtime.h>
#include <cuda_fp16.h>
#include <cstdint>

#define BATCH  256
#define DIM    4096
#define BD     (BATCH * DIM)
#define NSTEPS 30

// Half-block stage: (128 A rows + NT W rows) x 128 bytes (64 f16 k-values)
#define HSB_MAX (256 * 128)
#define SMEM_BYTES (2 * 3 * HSB_MAX)     // 196608 B

// ---------------- persistent device scratch ----------------
__device__ __half gW0[(size_t)DIM * DIM];
__device__ __half gW1[(size_t)DIM * DIM];
__device__ __half gW2[(size_t)DIM * DIM];
__device__ __half gW3[(size_t)DIM * DIM];
__device__ __half gW4[(size_t)DIM * DIM];
__device__ float  g_sf[2][3][BD];        // fp32 state, double buffered
__device__ __half g_sh[2][3][BD];        // f16 state copy (MMA operand)
__device__ __half g_s3h[BD];             // f16 of data layer
__device__ float  g_top[BD];             // s3 @ W4^T (constant across steps)

__device__ __forceinline__ void cp16(uint32_t sdst, const void* gsrc) {
    asm volatile("cp.async.cg.shared.global [%0], [%1], 16;\n" :: "r"(sdst), "l"(gsrc));
}
__device__ __forceinline__ void cp_commit() { asm volatile("cp.async.commit_group;\n"); }
__device__ __forceinline__ void cp_wait1()  { asm volatile("cp.async.wait_group 1;\n"); }
__device__ __forceinline__ void hbar(int id) {
    asm volatile("bar.sync %0, %1;" :: "r"(id), "r"(128) : "memory");
}
__device__ __forceinline__ void ldsm4(uint32_t r[4], uint32_t saddr) {
    asm volatile("ldmatrix.sync.aligned.m8n8.x4.shared.b16 {%0,%1,%2,%3}, [%4];"
        : "=r"(r[0]), "=r"(r[1]), "=r"(r[2]), "=r"(r[3]) : "r"(saddr));
}
__device__ __forceinline__ void mma16(float c[4], const uint32_t a[4], const uint32_t b[2]) {
    asm volatile(
        "mma.sync.aligned.m16n8k16.row.col.f32.f16.f16.f32 "
        "{%0,%1,%2,%3},{%4,%5,%6,%7},{%8,%9},{%0,%1,%2,%3};\n"
        : "+f"(c[0]), "+f"(c[1]), "+f"(c[2]), "+f"(c[3])
        : "f"(c[0]) /*dummy*/, "r"(a[0]), "r"(a[1]), "r"(a[2]), "r"(a[3]), "r"(b[0]), "r"(b[1]));
}

// corrected mma16 (no dummy operand)
__device__ __forceinline__ void mma16b(float c[4], const uint32_t a[4], const uint32_t b[2]) {
    asm volatile(
        "mma.sync.aligned.m16n8k16.row.col.f32.f16.f16.f32 "
        "{%0,%1,%2,%3},{%4,%5,%6,%7},{%8,%9},{%0,%1,%2,%3};\n"
        : "+f"(c[0]), "+f"(c[1]), "+f"(c[2]), "+f"(c[3])
        : "r"(a[0]), "r"(a[1]), "r"(a[2]), "r"(a[3]), "r"(b[0]), "r"(b[1]));
}

// ---------------- fused GEMM(+update) block-unit, 2 independent halves ----------------
// C[256, NT] = A0[256,4096] @ W0p[NT,4096]^T  (+ tiles t>=64: A1 @ W1p^T)
// 256 threads = 2 halves x 4 warps. Half h owns rows [h*128, h*128+128).
// NT=128: warp tile 64x64 (MI=4, warps 2x2). NT=64: warp tile 32x64 (MI=2, warps 4x1).
template <int NT, bool RAW>
__device__ __forceinline__ void gemm_unit(
    char* dsm, int nTiles,
    const __half* __restrict__ A0, const __half* __restrict__ W0p,
    const __half* __restrict__ A1, const __half* __restrict__ W1p,
    int nBase,
    const float* __restrict__ oldS, float* __restrict__ newSf,
    __half* __restrict__ newSh, const float* __restrict__ bias,
    const float* __restrict__ topP, float* __restrict__ rawOut)
{
    constexpr int MI  = (NT == 128) ? 4 : 2;     // m16 tiles per warp
    constexpr int WTM = MI * 16;                 // warp M extent (64 or 32)
    constexpr int HSB = (128 + NT) * 128;        // stage bytes per half

    const int tid   = threadIdx.x;
    const int warp  = tid >> 5;
    const int lane  = tid & 31;
    const int half  = warp >> 2;                 // 0 or 1
    const int hwarp = warp & 3;
    const int htid  = tid & 127;
    const int lq    = lane >> 2;
    const int lr    = lane & 3;
    const int warpM = (NT == 128) ? (hwarp >> 1) : hwarp;   // 0..1 or 0..3
    const int warpN = (NT == 128) ? (hwarp & 1)  : 0;       // 0..1 or 0

    const uint32_t smH_b = (uint32_t)__cvta_generic_to_shared(dsm) + half * (3 * HSB);
    const int msk = lane & 7;                    // swizzle mask

    // ldmatrix row-base byte offsets (swizzle chunk added per ks)
    const int aKh = lane >> 4;                   // k-half select for A
    const int bKh = (lane >> 3) & 1;             // k-half select for B
    int aByte[MI];
    #pragma unroll
    for (int mi = 0; mi < MI; mi++) {
        int row = warpM * WTM + mi * 16 + (lane & 7) + 8 * ((lane >> 3) & 1);
        aByte[mi] = row * 128;
    }
    int bByte[4];                                // 8 n8-tiles -> 4 ldsm4
    #pragma unroll
    for (int j = 0; j < 4; j++) {
        int row = 128 + warpN * 64 + j * 16 + (lane & 7) + 8 * (lane >> 4);
        bByte[j] = row * 128;
    }

    float acc[MI][8][4];
    #pragma unroll
    for (int mi = 0; mi < MI; mi++)
        #pragma unroll
        for (int ni = 0; ni < 8; ni++)
            #pragma unroll
            for (int f = 0; f < 4; f++) acc[mi][ni][f] = 0.0f;

    // ---- async load of one K-tile (64 f16 cols) into this half's stage s ----
    auto load_tile = [&](int s, int t) {
        const __half* A = (t < 64) ? A0 : A1;
        const __half* W = (t < 64) ? W0p : W1p;
        const int kOff = (t & 63) * 64;
        const uint32_t stA = smH_b + s * HSB;
        #pragma unroll
        for (int j = 0; j < 8; j++) {            // A: 128 rows x 8 chunks / 128 thr
            int f = htid + 128 * j;
            int row = f >> 3, c = f & 7;
            cp16(stA + row * 128 + ((c ^ (row & 7)) << 4),
                 A + (size_t)(half * 128 + row) * DIM + kOff + c * 8);
        }
        #pragma unroll
        for (int j = 0; j < NT / 16; j++) {      // W: NT rows x 8 chunks / 128 thr
            int f = htid + 128 * j;
            int row = f >> 3, c = f & 7;
            cp16(stA + 16384 + row * 128 + ((c ^ (row & 7)) << 4),
                 W + (size_t)row * DIM + kOff + c * 8);
        }
    };

    load_tile(0, 0); cp_commit();
    load_tile(1, 1); cp_commit();

    uint32_t afr[2][MI][4];
    uint32_t bfr[2][4][4];

    auto load_frag = [&](uint32_t stB, int ks, int pb) {
        #pragma unroll
        for (int mi = 0; mi < MI; mi++)
            ldsm4(afr[pb][mi], stB + aByte[mi] + (((2 * ks + aKh) ^ msk) << 4));
        #pragma unroll
        for (int j = 0; j < 4; j++)
            ldsm4(bfr[pb][j], stB + bByte[j] + (((2 * ks + bKh) ^ msk) << 4));
    };

    for (int t = 0; t < nTiles; t++) {
        cp_wait1();
        hbar(half + 1);
        if (t + 2 < nTiles) load_tile((t + 2) % 3, t + 2);
        cp_commit();

        const uint32_t stB = smH_b + (uint32_t)((t % 3) * HSB);
        load_frag(stB, 0, 0);
        #pragma unroll
        for (int ks = 0; ks < 4; ks++) {
            const int pb = ks & 1;
            if (ks < 3) load_frag(stB, ks + 1, pb ^ 1);
            #pragma unroll
            for (int mi = 0; mi < MI; mi++)
                #pragma unroll
                for (int ni = 0; ni < 8; ni++)
                    mma16b(acc[mi][ni], afr[pb][mi], &bfr[pb][ni >> 1][(ni & 1) * 2]);
        }
    }

    // ---- fused epilogue (each output element owned by this block) ----
    #pragma unroll
    for (int mi = 0; mi < MI; mi++) {
        #pragma unroll
        for (int ni = 0; ni < 8; ni++) {
            int r0 = half * 128 + warpM * WTM + mi * 16 + lq;
            int c0 = nBase + warpN * 64 + ni * 8 + 2 * lr;
            #pragma unroll
            for (int h = 0; h < 2; h++) {
                int r = r0 + 8 * h;
                #pragma unroll
                for (int g = 0; g < 2; g++) {
                    int c = c0 + g;
                    float y = acc[mi][ni][2 * h + g];
                    size_t idx = (size_t)r * DIM + c;
                    if (RAW) {
                        rawOut[idx] = y;
                    } else {
                        y += bias[c];
                        if (topP) y += topP[idx];
                        float ns = 0.5f * oldS[idx] + 0.5f * y;
                        ns = fminf(fmaxf(ns, 0.0f), 1.0f);
                        newSf[idx] = ns;
                        newSh[idx] = __float2half_rn(ns);
                    }
                }
            }
        }
    }
}

// -------- one relaxation step: 128 equal-work blocks, one wave --------
__global__ void __launch_bounds__(256, 1) step_kernel(
    int p, const float* __restrict__ b0, const float* __restrict__ b2,
    const float* __restrict__ b4)
{
    extern __shared__ char dsm[];
    const int bid = blockIdx.x;
    const int q = p ^ 1;
    if (bid < 32) {                 // s0' <- clip(.5 s0 + .5 (s1 @ W0^T + b0))
        const int nB = bid * 128;
        gemm_unit<128, false>(dsm, 64, g_sh[p][1], gW0 + (size_t)nB * DIM,
                              g_sh[p][1], gW0 + (size_t)nB * DIM, nB,
                              g_sf[p][0], g_sf[q][0], g_sh[q][0], b0, nullptr, nullptr);
    } else if (bid < 96) {          // s1' <- clip(.5 s1 + .5 (s2 @ W2^T + s0 @ W1^T + b2))
        const int nB = (bid - 32) * 64;
        gemm_unit<64, false>(dsm, 128, g_sh[p][2], gW2 + (size_t)nB * DIM,
                             g_sh[p][0], gW1 + (size_t)nB * DIM, nB,
                             g_sf[p][1], g_sf[q][1], g_sh[q][1], b2, nullptr, nullptr);
    } else {                        // s2' <- clip(.5 s2 + .5 (s1 @ W3^T + top + b4))
        const int nB = (bid - 96) * 128;
        gemm_unit<128, false>(dsm, 64, g_sh[p][1], gW3 + (size_t)nB * DIM,
                              g_sh[p][1], gW3 + (size_t)nB * DIM, nB,
                              g_sf[p][2], g_sf[q][2], g_sh[q][2], b4, g_top, nullptr);
    }
}

__global__ void __launch_bounds__(256, 1) top_kernel()
{
    extern __shared__ char dsm[];
    const int nB = blockIdx.x * 128;
    gemm_unit<128, true>(dsm, 64, g_s3h, gW4 + (size_t)nB * DIM,
                         g_s3h, gW4 + (size_t)nB * DIM, nB,
                         nullptr, nullptr, nullptr, nullptr, nullptr, g_top);
}

// -------- setup / teardown --------
__global__ void wconv_kernel(const float* __restrict__ w0, const float* __restrict__ w1,
                             const float* __restrict__ w2, const float* __restrict__ w3,
                             const float* __restrict__ w4)
{
    const float* src;
    __half* dst;
    switch (blockIdx.y) {
        case 0: src = w0; dst = gW0; break;
        case 1: src = w1; dst = gW1; break;
        case 2: src = w2; dst = gW2; break;
        case 3: src = w3; dst = gW3; break;
        default: src = w4; dst = gW4; break;
    }
    size_t i = ((size_t)blockIdx.x * blockDim.x + threadIdx.x) * 4;
    float4 v = *(const float4*)(src + i);
    *(__half2*)(dst + i)     = __floats2half2_rn(v.x, v.y);
    *(__half2*)(dst + i + 2) = __floats2half2_rn(v.z, v.w);
}

__global__ void init_kernel(const float* __restrict__ s0, const float* __restrict__ s1,
                            const float* __restrict__ s2, const float* __restrict__ s3)
{
    int i = blockIdx.x * blockDim.x + threadIdx.x;
    float v0 = s0[i], v1 = s1[i], v2 = s2[i];
    g_sf[0][0][i] = v0; g_sh[0][0][i] = __float2half_rn(v0);
    g_sf[0][1][i] = v1; g_sh[0][1][i] = __float2half_rn(v1);
    g_sf[0][2][i] = v2; g_sh[0][2][i] = __float2half_rn(v2);
    g_s3h[i] = __float2half_rn(s3[i]);
}

__global__ void out_kernel(float* __restrict__ out)
{
    int i = blockIdx.x * blockDim.x + threadIdx.x;
    out[i]          = g_sf[0][0][i];
    out[BD + i]     = g_sf[0][1][i];
    out[2 * BD + i] = g_sf[0][2][i];
}

extern "C" void kernel_launch(void* const* d_in, const int* in_sizes, int n_in,
                              void* d_out, int out_size)
{
    const float* s0 = (const float*)d_in[0];
    const float* s1 = (const float*)d_in[1];
    const float* s2 = (const float*)d_in[2];
    const float* s3 = (const float*)d_in[3];
    const float* W0 = (const float*)d_in[4];
    const float* b0 = (const float*)d_in[5];
    const float* W1 = (const float*)d_in[6];
    const float* W2 = (const float*)d_in[7];
    const float* b2 = (const float*)d_in[8];
    const float* W3 = (const float*)d_in[9];
    const float* W4 = (const float*)d_in[10];
    const float* b4 = (const float*)d_in[11];

    static_assert(SMEM_BYTES <= 227 * 1024, "smem budget");
    cudaFuncSetAttribute(step_kernel, cudaFuncAttributeMaxDynamicSharedMemorySize, SMEM_BYTES);
    cudaFuncSetAttribute(top_kernel,  cudaFuncAttributeMaxDynamicSharedMemorySize, SMEM_BYTES);

    wconv_kernel<<<dim3(DIM * DIM / 4 / 256, 5), 256>>>(W0, W1, W2, W3, W4);
    init_kernel<<<BD / 256, 256>>>(s0, s1, s2, s3);

    top_kernel<<<32, 256, SMEM_BYTES>>>();

    for (int t = 0; t < NSTEPS; t++)
        step_kernel<<<128, 256, SMEM_BYTES>>>(t & 1, b0, b2, b4);

    out_kernel<<<BD / 256, 256>>>((float*)d_out);
}

// round 9
// speedup vs baseline: 1.1039x; 1.1039x over previous
#include <cuda_runtime.h>
#include <cuda_fp16.h>
#include <cstdint>

#define BATCH  256
#define DIM    4096
#define BD     (BATCH * DIM)
#define NSTEPS 30

// Half-block stage: (128 A rows + NT W rows) x 128 bytes (64 f16 k-values)
#define HSB_MAX (256 * 128)
#define SMEM_BYTES (2 * 3 * HSB_MAX)     // 196608 B

// ---------------- persistent device scratch ----------------
__device__ __half gW0[(size_t)DIM * DIM];
__device__ __half gW1[(size_t)DIM * DIM];
__device__ __half gW2[(size_t)DIM * DIM];
__device__ __half gW3[(size_t)DIM * DIM];
__device__ __half gW4[(size_t)DIM * DIM];
__device__ float  g_sf[2][3][BD];        // fp32 state, double buffered
__device__ __half g_sh[2][3][BD];        // f16 state copy (MMA operand)
__device__ __half g_s3h[BD];             // f16 of data layer
__device__ float  g_top[BD];             // s3 @ W4^T (constant across steps)

__device__ __forceinline__ void cp16(uint32_t sdst, const void* gsrc) {
    asm volatile("cp.async.cg.shared.global [%0], [%1], 16;\n" :: "r"(sdst), "l"(gsrc));
}
__device__ __forceinline__ void cp_commit() { asm volatile("cp.async.commit_group;\n"); }
__device__ __forceinline__ void cp_wait1()  { asm volatile("cp.async.wait_group 1;\n"); }
__device__ __forceinline__ void hbar(int id) {
    asm volatile("bar.sync %0, %1;" :: "r"(id), "r"(256) : "memory");
}
__device__ __forceinline__ void ldsm4(uint32_t r[4], uint32_t saddr) {
    asm volatile("ldmatrix.sync.aligned.m8n8.x4.shared.b16 {%0,%1,%2,%3}, [%4];"
        : "=r"(r[0]), "=r"(r[1]), "=r"(r[2]), "=r"(r[3]) : "r"(saddr));
}
__device__ __forceinline__ void mma16(float c[4], const uint32_t a[4], const uint32_t b[2]) {
    asm volatile(
        "mma.sync.aligned.m16n8k16.row.col.f32.f16.f16.f32 "
        "{%0,%1,%2,%3},{%4,%5,%6,%7},{%8,%9},{%0,%1,%2,%3};\n"
        : "+f"(c[0]), "+f"(c[1]), "+f"(c[2]), "+f"(c[3])
        : "r"(a[0]), "r"(a[1]), "r"(a[2]), "r"(a[3]), "r"(b[0]), "r"(b[1]));
}

// ---------------- fused GEMM(+update) block-unit, 2 independent halves ----------------
// C[256, NT] = A0[256,4096] @ W0p[NT,4096]^T  (+ tiles t>=64: A1 @ W1p^T)
// 512 threads = 2 halves x 8 warps. Half h owns rows [h*128, h*128+128).
// Warp tile 32 x (NT/2): warpM = hwarp>>1 (0..3), warpN = hwarp&1.
template <int NT, bool RAW>
__device__ __forceinline__ void gemm_unit(
    char* dsm, int nTiles,
    const __half* __restrict__ A0, const __half* __restrict__ W0p,
    const __half* __restrict__ A1, const __half* __restrict__ W1p,
    int nBase,
    const float* __restrict__ oldS, float* __restrict__ newSf,
    __half* __restrict__ newSh, const float* __restrict__ bias,
    const float* __restrict__ topP, float* __restrict__ rawOut)
{
    constexpr int NI  = NT / 16;                 // n8 tiles per warp (8 or 4)
    constexpr int HSB = (128 + NT) * 128;        // stage bytes per half

    const int tid   = threadIdx.x;
    const int warp  = tid >> 5;
    const int lane  = tid & 31;
    const int half  = warp >> 3;                 // 0 or 1
    const int hwarp = warp & 7;
    const int htid  = tid & 255;
    const int lq    = lane >> 2;
    const int lr    = lane & 3;
    const int warpM = hwarp >> 1;                // 0..3 (32-row tiles)
    const int warpN = hwarp & 1;

    const uint32_t smH_b = (uint32_t)__cvta_generic_to_shared(dsm) + half * (3 * HSB);
    const int msk = lane & 7;                    // swizzle mask

    // ldmatrix row-base byte offsets (swizzle chunk added per ks)
    const int aKh = lane >> 4;                   // k-half select for A
    const int bKh = (lane >> 3) & 1;             // k-half select for B
    int aByte[2];
    #pragma unroll
    for (int mi = 0; mi < 2; mi++) {
        int row = warpM * 32 + mi * 16 + (lane & 7) + 8 * ((lane >> 3) & 1);
        aByte[mi] = row * 128;
    }
    int bByte[NI / 2];
    #pragma unroll
    for (int j = 0; j < NI / 2; j++) {
        int row = 128 + warpN * (NI * 8) + j * 16 + (lane & 7) + 8 * (lane >> 4);
        bByte[j] = row * 128;
    }

    float acc[2][NI][4];
    #pragma unroll
    for (int mi = 0; mi < 2; mi++)
        #pragma unroll
        for (int ni = 0; ni < NI; ni++)
            #pragma unroll
            for (int f = 0; f < 4; f++) acc[mi][ni][f] = 0.0f;

    // ---- async load of one K-tile (64 f16 cols) into this half's stage s ----
    auto load_tile = [&](int s, int t) {
        const __half* A = (t < 64) ? A0 : A1;
        const __half* W = (t < 64) ? W0p : W1p;
        const int kOff = (t & 63) * 64;
        const uint32_t stA = smH_b + s * HSB;
        #pragma unroll
        for (int j = 0; j < 4; j++) {            // A: 128 rows x 8 chunks
            int f = htid + 256 * j;
            int row = f >> 3, c = f & 7;
            cp16(stA + row * 128 + ((c ^ (row & 7)) << 4),
                 A + (size_t)(half * 128 + row) * DIM + kOff + c * 8);
        }
        #pragma unroll
        for (int j = 0; j < NT / 32; j++) {      // W: NT rows x 8 chunks
            int f = htid + 256 * j;
            int row = f >> 3, c = f & 7;
            cp16(stA + 16384 + row * 128 + ((c ^ (row & 7)) << 4),
                 W + (size_t)row * DIM + kOff + c * 8);
        }
    };

    load_tile(0, 0); cp_commit();
    load_tile(1, 1); cp_commit();

    int stage = 0;
    for (int t = 0; t < nTiles; t++) {
        cp_wait1();
        hbar(half + 1);
        if (t + 2 < nTiles) {
            int s2 = stage + 2; if (s2 >= 3) s2 -= 3;
            load_tile(s2, t + 2);
        }
        cp_commit();

        const uint32_t stB = smH_b + (uint32_t)(stage * HSB);

        // hoist ALL A fragments for this tile (8 independent ldsm4, high MLP)
        uint32_t afr[4][2][4];                   // [ks][mi][4]
        #pragma unroll
        for (int ks = 0; ks < 4; ks++)
            #pragma unroll
            for (int mi = 0; mi < 2; mi++)
                ldsm4(afr[ks][mi], stB + aByte[mi] + (((2 * ks + aKh) ^ msk) << 4));

        #pragma unroll
        for (int ks = 0; ks < 4; ks++) {
            uint32_t bfr[NI / 2][4];
            #pragma unroll
            for (int j = 0; j < NI / 2; j++)
                ldsm4(bfr[j], stB + bByte[j] + (((2 * ks + bKh) ^ msk) << 4));
            #pragma unroll
            for (int mi = 0; mi < 2; mi++)
                #pragma unroll
                for (int ni = 0; ni < NI; ni++)
                    mma16(acc[mi][ni], afr[ks][mi], &bfr[ni >> 1][(ni & 1) * 2]);
        }
        if (++stage == 3) stage = 0;
    }

    // ---- fused epilogue (each output element owned by this block) ----
    #pragma unroll
    for (int mi = 0; mi < 2; mi++) {
        #pragma unroll
        for (int ni = 0; ni < NI; ni++) {
            int r0 = half * 128 + warpM * 32 + mi * 16 + lq;
            int c0 = nBase + warpN * (NI * 8) + ni * 8 + 2 * lr;
            #pragma unroll
            for (int h = 0; h < 2; h++) {
                int r = r0 + 8 * h;
                #pragma unroll
                for (int g = 0; g < 2; g++) {
                    int c = c0 + g;
                    float y = acc[mi][ni][2 * h + g];
                    size_t idx = (size_t)r * DIM + c;
                    if (RAW) {
                        rawOut[idx] = y;
                    } else {
                        y += bias[c];
                        if (topP) y += topP[idx];
                        float ns = 0.5f * oldS[idx] + 0.5f * y;
                        ns = fminf(fmaxf(ns, 0.0f), 1.0f);
                        newSf[idx] = ns;
                        newSh[idx] = __float2half_rn(ns);
                    }
                }
            }
        }
    }
}

// -------- one relaxation step: 128 equal-work blocks, one wave --------
__global__ void __launch_bounds__(512, 1) step_kernel(
    int p, const float* __restrict__ b0, const float* __restrict__ b2,
    const float* __restrict__ b4)
{
    extern __shared__ char dsm[];
    const int bid = blockIdx.x;
    const int q = p ^ 1;
    if (bid < 32) {                 // s0' <- clip(.5 s0 + .5 (s1 @ W0^T + b0))
        const int nB = bid * 128;
        gemm_unit<128, false>(dsm, 64, g_sh[p][1], gW0 + (size_t)nB * DIM,
                              g_sh[p][1], gW0 + (size_t)nB * DIM, nB,
                              g_sf[p][0], g_sf[q][0], g_sh[q][0], b0, nullptr, nullptr);
    } else if (bid < 96) {          // s1' <- clip(.5 s1 + .5 (s2 @ W2^T + s0 @ W1^T + b2))
        const int nB = (bid - 32) * 64;
        gemm_unit<64, false>(dsm, 128, g_sh[p][2], gW2 + (size_t)nB * DIM,
                             g_sh[p][0], gW1 + (size_t)nB * DIM, nB,
                             g_sf[p][1], g_sf[q][1], g_sh[q][1], b2, nullptr, nullptr);
    } else {                        // s2' <- clip(.5 s2 + .5 (s1 @ W3^T + top + b4))
        const int nB = (bid - 96) * 128;
        gemm_unit<128, false>(dsm, 64, g_sh[p][1], gW3 + (size_t)nB * DIM,
                              g_sh[p][1], gW3 + (size_t)nB * DIM, nB,
                              g_sf[p][2], g_sf[q][2], g_sh[q][2], b4, g_top, nullptr);
    }
}

__global__ void __launch_bounds__(512, 1) top_kernel()
{
    extern __shared__ char dsm[];
    const int nB = blockIdx.x * 128;
    gemm_unit<128, true>(dsm, 64, g_s3h, gW4 + (size_t)nB * DIM,
                         g_s3h, gW4 + (size_t)nB * DIM, nB,
                         nullptr, nullptr, nullptr, nullptr, nullptr, g_top);
}

// -------- setup / teardown --------
__global__ void wconv_kernel(const float* __restrict__ w0, const float* __restrict__ w1,
                             const float* __restrict__ w2, const float* __restrict__ w3,
                             const float* __restrict__ w4)
{
    const float* src;
    __half* dst;
    switch (blockIdx.y) {
        case 0: src = w0; dst = gW0; break;
        case 1: src = w1; dst = gW1; break;
        case 2: src = w2; dst = gW2; break;
        case 3: src = w3; dst = gW3; break;
        default: src = w4; dst = gW4; break;
    }
    size_t i = ((size_t)blockIdx.x * blockDim.x + threadIdx.x) * 4;
    float4 v = *(const float4*)(src + i);
    *(__half2*)(dst + i)     = __floats2half2_rn(v.x, v.y);
    *(__half2*)(dst + i + 2) = __floats2half2_rn(v.z, v.w);
}

__global__ void init_kernel(const float* __restrict__ s0, const float* __restrict__ s1,
                            const float* __restrict__ s2, const float* __restrict__ s3)
{
    int i = blockIdx.x * blockDim.x + threadIdx.x;
    float v0 = s0[i], v1 = s1[i], v2 = s2[i];
    g_sf[0][0][i] = v0; g_sh[0][0][i] = __float2half_rn(v0);
    g_sf[0][1][i] = v1; g_sh[0][1][i] = __float2half_rn(v1);
    g_sf[0][2][i] = v2; g_sh[0][2][i] = __float2half_rn(v2);
    g_s3h[i] = __float2half_rn(s3[i]);
}

__global__ void out_kernel(float* __restrict__ out)
{
    int i = blockIdx.x * blockDim.x + threadIdx.x;
    out[i]          = g_sf[0][0][i];
    out[BD + i]     = g_sf[0][1][i];
    out[2 * BD + i] = g_sf[0][2][i];
}

extern "C" void kernel_launch(void* const* d_in, const int* in_sizes, int n_in,
                              void* d_out, int out_size)
{
    const float* s0 = (const float*)d_in[0];
    const float* s1 = (const float*)d_in[1];
    const float* s2 = (const float*)d_in[2];
    const float* s3 = (const float*)d_in[3];
    const float* W0 = (const float*)d_in[4];
    const float* b0 = (const float*)d_in[5];
    const float* W1 = (const float*)d_in[6];
    const float* W2 = (const float*)d_in[7];
    const float* b2 = (const float*)d_in[8];
    const float* W3 = (const float*)d_in[9];
    const float* W4 = (const float*)d_in[10];
    const float* b4 = (const float*)d_in[11];

    static_assert(SMEM_BYTES <= 227 * 1024, "smem budget");
    cudaFuncSetAttribute(step_kernel, cudaFuncAttributeMaxDynamicSharedMemorySize, SMEM_BYTES);
    cudaFuncSetAttribute(top_kernel,  cudaFuncAttributeMaxDynamicSharedMemorySize, SMEM_BYTES);

    wconv_kernel<<<dim3(DIM * DIM / 4 / 256, 5), 256>>>(W0, W1, W2, W3, W4);
    init_kernel<<<BD / 256, 256>>>(s0, s1, s2, s3);

    top_kernel<<<32, 512, SMEM_BYTES>>>();

    for (int t = 0; t < NSTEPS; t++)
        step_kernel<<<128, 512, SMEM_BYTES>>>(t & 1, b0, b2, b4);

    out_kernel<<<BD / 256, 256>>>((float*)d_out);
}

// round 10
// speedup vs baseline: 1.2951x; 1.1732x over previous
#include <cuda_runtime.h>
#include <cuda_fp16.h>
#include <cstdint>

#define BATCH  256
#define DIM    4096
#define BD     (BATCH * DIM)
#define NSTEPS 30
#define SMEM_BYTES 196608   // 2 halves x 3 stages x 32KB (NT=128 case)

// ---------------- persistent device scratch (packed, pre-swizzled) ----------------
// Weights: [N/NTp][64 kTiles][NTp rows][64 halfs], chunk c of row stored at c^(row&7)
__device__ __align__(128) __half gW0[(size_t)DIM * DIM];   // NTp=128
__device__ __align__(128) __half gW1[(size_t)DIM * DIM];   // NTp=64
__device__ __align__(128) __half gW2[(size_t)DIM * DIM];   // NTp=64
__device__ __align__(128) __half gW3[(size_t)DIM * DIM];   // NTp=128
__device__ __align__(128) __half gW4[(size_t)DIM * DIM];   // NTp=128
__device__ float g_sf[2][3][BD];                            // fp32 state (plain)
__device__ __align__(128) __half g_sh[2][3][BD];            // f16 state, panel-packed [64][256][64]
__device__ __align__(128) __half g_s3h[BD];                 // f16 data layer, panel-packed
__device__ float g_top[BD];                                 // s3 @ W4^T (plain fp32)

// ---------------- helpers ----------------
__device__ __forceinline__ uint32_t s2u(const void* p) {
    return (uint32_t)__cvta_generic_to_shared(p);
}
__device__ __forceinline__ void mbar_init(uint32_t a, uint32_t c) {
    asm volatile("mbarrier.init.shared.b64 [%0], %1;" :: "r"(a), "r"(c) : "memory");
}
__device__ __forceinline__ void mbar_arrive(uint32_t a) {
    asm volatile("mbarrier.arrive.shared.b64 _, [%0];" :: "r"(a) : "memory");
}
__device__ __forceinline__ void mbar_expect(uint32_t a, uint32_t tx) {
    asm volatile("mbarrier.arrive.expect_tx.shared.b64 _, [%0], %1;" :: "r"(a), "r"(tx) : "memory");
}
__device__ __forceinline__ void mbar_wait(uint32_t a, uint32_t ph) {
    asm volatile(
        "{\n\t.reg .pred P;\n"
        "WL%=:\n\t"
        "mbarrier.try_wait.parity.shared.b64 P, [%0], %1, 0x989680;\n\t"
        "@P bra WD%=;\n\t"
        "bra WL%=;\n"
        "WD%=:\n\t}"
        :: "r"(a), "r"(ph) : "memory");
}
__device__ __forceinline__ void bulkcp(uint32_t d, const void* s, uint32_t n, uint32_t mb) {
    asm volatile(
        "cp.async.bulk.shared::cluster.global.mbarrier::complete_tx::bytes [%0], [%1], %2, [%3];"
        :: "r"(d), "l"(s), "r"(n), "r"(mb) : "memory");
}
__device__ __forceinline__ void ldsm4(uint32_t r[4], uint32_t saddr) {
    asm volatile("ldmatrix.sync.aligned.m8n8.x4.shared.b16 {%0,%1,%2,%3}, [%4];"
        : "=r"(r[0]), "=r"(r[1]), "=r"(r[2]), "=r"(r[3]) : "r"(saddr));
}
__device__ __forceinline__ void mma16(float c[4], const uint32_t a[4], const uint32_t b[2]) {
    asm volatile(
        "mma.sync.aligned.m16n8k16.row.col.f32.f16.f16.f32 "
        "{%0,%1,%2,%3},{%4,%5,%6,%7},{%8,%9},{%0,%1,%2,%3};\n"
        : "+f"(c[0]), "+f"(c[1]), "+f"(c[2]), "+f"(c[3])
        : "r"(a[0]), "r"(a[1]), "r"(a[2]), "r"(a[3]), "r"(b[0]), "r"(b[1]));
}

// ---------------- fused GEMM(+update) block-unit, 2 independent halves ----------------
// C[256, NT] = A0[256,4096] @ W0p^T (+ tiles t>=64: A1 @ W1p^T). Panels pre-swizzled.
// 512 threads = 2 halves x 8 warps, warp tile 32 x (NT/2).
template <int NT, bool RAW>
__device__ __forceinline__ void gemm_unit(
    char* dsm, int nTiles,
    const __half* __restrict__ A0, const __half* __restrict__ W0p,
    const __half* __restrict__ A1, const __half* __restrict__ W1p,
    int nBase,
    const float* __restrict__ oldS, float* __restrict__ newSf,
    __half* __restrict__ newShPan, const float* __restrict__ bias,
    const float* __restrict__ topP, float* __restrict__ rawOut)
{
    constexpr int NI  = NT / 16;                 // n8 tiles per warp (8 or 4)
    constexpr int HSB = 16384 + NT * 128;        // stage bytes per half
    constexpr uint32_t TXB = 16384 + NT * 128;   // expected tx bytes per stage

    __shared__ uint64_t mbF[2][3], mbE[2][3];

    const int tid   = threadIdx.x;
    const int warp  = tid >> 5;
    const int lane  = tid & 31;
    const int half  = warp >> 3;
    const int hwarp = warp & 7;
    const int lq    = lane >> 2;
    const int lr    = lane & 3;
    const int warpM = hwarp >> 1;                // 0..3 (32-row tiles)
    const int warpN = hwarp & 1;

    const uint32_t smH_b = s2u(dsm) + half * (3 * HSB);
    const uint32_t mbF_b = s2u(&mbF[half][0]);
    const uint32_t mbE_b = s2u(&mbE[half][0]);

    if (tid == 0) {
        #pragma unroll
        for (int h = 0; h < 2; h++)
            #pragma unroll
            for (int s = 0; s < 3; s++) {
                mbar_init(s2u(&mbF[h][s]), 1);   // 1 expect_tx arrival + tx bytes
                mbar_init(s2u(&mbE[h][s]), 8);   // 8 consumer warps
            }
    }
    __syncthreads();

    const bool prod = (hwarp == 0 && lane == 0);

    auto issue = [&](int s, int t) {             // producer thread only
        const __half* A = (t < 64) ? A0 : A1;
        const __half* W = (t < 64) ? W0p : W1p;
        const int tt = t & 63;
        const uint32_t mb = mbF_b + 8 * s;
        const uint32_t dA = smH_b + s * HSB;
        mbar_expect(mb, TXB);
        bulkcp(dA, A + (size_t)(tt * 256 + half * 128) * 64, 16384, mb);
        bulkcp(dA + 16384, W + (size_t)tt * (NT * 64), NT * 128, mb);
    };

    if (prod) {
        issue(0, 0); issue(1, 1); issue(2, 2);
    }

    // fragment addressing (identical to R7; rows local to half)
    const int msk = lane & 7;
    const int aKh = lane >> 4;
    const int bKh = (lane >> 3) & 1;
    int aByte[2];
    #pragma unroll
    for (int mi = 0; mi < 2; mi++) {
        int row = warpM * 32 + mi * 16 + (lane & 7) + 8 * ((lane >> 3) & 1);
        aByte[mi] = row * 128;
    }
    int bByte[NI / 2];
    #pragma unroll
    for (int j = 0; j < NI / 2; j++) {
        int row = 128 + warpN * (NI * 8) + j * 16 + (lane & 7) + 8 * (lane >> 4);
        bByte[j] = row * 128;
    }

    float acc[2][NI][4];
    #pragma unroll
    for (int mi = 0; mi < 2; mi++)
        #pragma unroll
        for (int ni = 0; ni < NI; ni++)
            #pragma unroll
            for (int f = 0; f < 4; f++) acc[mi][ni][f] = 0.0f;

    uint32_t afr[2][2][4];
    uint32_t bfr[2][NI / 2][4];
    auto load_frag = [&](uint32_t stB, int ks, int pb) {
        #pragma unroll
        for (int mi = 0; mi < 2; mi++)
            ldsm4(afr[pb][mi], stB + aByte[mi] + (((2 * ks + aKh) ^ msk) << 4));
        #pragma unroll
        for (int j = 0; j < NI / 2; j++)
            ldsm4(bfr[pb][j], stB + bByte[j] + (((2 * ks + bKh) ^ msk) << 4));
    };

    for (int t = 0; t < nTiles; t++) {
        const int s = t - (t / 3) * 3;
        const uint32_t ph = (uint32_t)((t / 3) & 1);
        mbar_wait(mbF_b + 8 * s, ph);

        const uint32_t stB = smH_b + (uint32_t)(s * HSB);
        load_frag(stB, 0, 0);
        #pragma unroll
        for (int ks = 0; ks < 4; ks++) {
            const int pb = ks & 1;
            if (ks < 3) load_frag(stB, ks + 1, pb ^ 1);
            #pragma unroll
            for (int mi = 0; mi < 2; mi++)
                #pragma unroll
                for (int ni = 0; ni < NI; ni++)
                    mma16(acc[mi][ni], afr[pb][mi], &bfr[pb][ni >> 1][(ni & 1) * 2]);
        }

        if (lane == 0) mbar_arrive(mbE_b + 8 * s);
        if (prod && t + 3 < nTiles) {
            mbar_wait(mbE_b + 8 * s, ph);        // all 8 warps done with this stage
            issue(s, t + 3);
        }
    }

    // ---- fused epilogue (each output element owned by this block) ----
    #pragma unroll
    for (int mi = 0; mi < 2; mi++) {
        #pragma unroll
        for (int ni = 0; ni < NI; ni++) {
            int r = half * 128 + warpM * 32 + mi * 16 + lq;
            int c0 = nBase + warpN * (NI * 8) + ni * 8 + 2 * lr;
            #pragma unroll
            for (int h = 0; h < 2; h++) {
                int rr = r + 8 * h;
                float y0 = acc[mi][ni][2 * h + 0];
                float y1 = acc[mi][ni][2 * h + 1];
                size_t idx = (size_t)rr * DIM + c0;
                if (RAW) {
                    *(float2*)(rawOut + idx) = make_float2(y0, y1);
                } else {
                    y0 += bias[c0];
                    y1 += bias[c0 + 1];
                    if (topP) { y0 += topP[idx]; y1 += topP[idx + 1]; }
                    float n0 = fminf(fmaxf(0.5f * oldS[idx]     + 0.5f * y0, 0.0f), 1.0f);
                    float n1 = fminf(fmaxf(0.5f * oldS[idx + 1] + 0.5f * y1, 0.0f), 1.0f);
                    *(float2*)(newSf + idx) = make_float2(n0, n1);
                    // packed-swizzled panel write for next step's bulk loads
                    uint32_t off = (uint32_t)(((c0 >> 6) * 256 + rr) * 64
                                   + ((((c0 & 63) >> 3) ^ (rr & 7)) * 8) + (c0 & 7));
                    *(__half2*)(newShPan + off) = __floats2half2_rn(n0, n1);
                }
            }
        }
    }
}

// -------- one relaxation step: 128 equal-work blocks, one wave --------
__global__ void __launch_bounds__(512, 1) step_kernel(
    int p, const float* __restrict__ b0, const float* __restrict__ b2,
    const float* __restrict__ b4)
{
    extern __shared__ __align__(1024) char dsm[];
    const int bid = blockIdx.x;
    const int q = p ^ 1;
    if (bid < 32) {                 // s0' <- clip(.5 s0 + .5 (s1 @ W0^T + b0))
        const int nB = bid * 128;
        gemm_unit<128, false>(dsm, 64, g_sh[p][1], gW0 + (size_t)nB * DIM,
                              g_sh[p][1], gW0 + (size_t)nB * DIM, nB,
                              g_sf[p][0], g_sf[q][0], g_sh[q][0], b0, nullptr, nullptr);
    } else if (bid < 96) {          // s1' <- clip(.5 s1 + .5 (s2 @ W2^T + s0 @ W1^T + b2))
        const int nB = (bid - 32) * 64;
        gemm_unit<64, false>(dsm, 128, g_sh[p][2], gW2 + (size_t)nB * DIM,
                             g_sh[p][0], gW1 + (size_t)nB * DIM, nB,
                             g_sf[p][1], g_sf[q][1], g_sh[q][1], b2, nullptr, nullptr);
    } else {                        // s2' <- clip(.5 s2 + .5 (s1 @ W3^T + top + b4))
        const int nB = (bid - 96) * 128;
        gemm_unit<128, false>(dsm, 64, g_sh[p][1], gW3 + (size_t)nB * DIM,
                              g_sh[p][1], gW3 + (size_t)nB * DIM, nB,
                              g_sf[p][2], g_sf[q][2], g_sh[q][2], b4, g_top, nullptr);
    }
}

__global__ void __launch_bounds__(512, 1) top_kernel()
{
    extern __shared__ __align__(1024) char dsm[];
    const int nB = blockIdx.x * 128;
    gemm_unit<128, true>(dsm, 64, g_s3h, gW4 + (size_t)nB * DIM,
                         g_s3h, gW4 + (size_t)nB * DIM, nB,
                         nullptr, nullptr, nullptr, nullptr, nullptr, g_top);
}

// -------- setup: pack + swizzle weights and state --------
__global__ void wconv_kernel(const float* __restrict__ w0, const float* __restrict__ w1,
                             const float* __restrict__ w2, const float* __restrict__ w3,
                             const float* __restrict__ w4)
{
    const float* src;
    __half* dst;
    int ntShift;                       // log2(NTp)
    switch (blockIdx.y) {
        case 0: src = w0; dst = gW0; ntShift = 7; break;
        case 1: src = w1; dst = gW1; ntShift = 6; break;
        case 2: src = w2; dst = gW2; ntShift = 6; break;
        case 3: src = w3; dst = gW3; ntShift = 7; break;
        default: src = w4; dst = gW4; ntShift = 7; break;
    }
    const int id = blockIdx.x * blockDim.x + threadIdx.x;   // 0 .. 2M-1 (16B chunks)
    const int n  = id >> 9;
    const int kc = id & 511;
    float4 v0 = *(const float4*)(src + (size_t)n * DIM + kc * 8);
    float4 v1 = *(const float4*)(src + (size_t)n * DIM + kc * 8 + 4);
    __half2 h[4] = { __floats2half2_rn(v0.x, v0.y), __floats2half2_rn(v0.z, v0.w),
                     __floats2half2_rn(v1.x, v1.y), __floats2half2_rn(v1.z, v1.w) };
    const int NTp = 1 << ntShift;
    const int row = n & (NTp - 1);
    const int nT  = n >> ntShift;
    const int kT  = kc >> 3;
    const int ch  = kc & 7;
    size_t off = ((size_t)(nT * 64 + kT) * NTp + row) * 64 + (size_t)((ch ^ (row & 7)) * 8);
    *(uint4*)(dst + off) = *(uint4*)h;
}

__global__ void init_kernel(const float* __restrict__ s0, const float* __restrict__ s1,
                            const float* __restrict__ s2, const float* __restrict__ s3)
{
    const int layer = blockIdx.y;      // 0..3 (3 = s3)
    const float* src = (layer == 0) ? s0 : (layer == 1) ? s1 : (layer == 2) ? s2 : s3;
    __half* pan = (layer == 3) ? g_s3h : g_sh[0][layer];
    const int id = blockIdx.x * blockDim.x + threadIdx.x;   // 0 .. BD/8-1
    const int row = id >> 9;
    const int kc  = id & 511;
    float4 v0 = *(const float4*)(src + (size_t)row * DIM + kc * 8);
    float4 v1 = *(const float4*)(src + (size_t)row * DIM + kc * 8 + 4);
    __half2 h[4] = { __floats2half2_rn(v0.x, v0.y), __floats2half2_rn(v0.z, v0.w),
                     __floats2half2_rn(v1.x, v1.y), __floats2half2_rn(v1.z, v1.w) };
    size_t off = ((size_t)(kc >> 3) * 256 + row) * 64 + (size_t)(((kc & 7) ^ (row & 7)) * 8);
    *(uint4*)(pan + off) = *(uint4*)h;
    if (layer < 3) {
        float* sf = g_sf[0][layer] + (size_t)row * DIM + kc * 8;
        *(float4*)sf = v0;
        *(float4*)(sf + 4) = v1;
    }
}

__global__ void out_kernel(float* __restrict__ out)
{
    int i = blockIdx.x * blockDim.x + threadIdx.x;
    out[i]          = g_sf[0][0][i];
    out[BD + i]     = g_sf[0][1][i];
    out[2 * BD + i] = g_sf[0][2][i];
}

extern "C" void kernel_launch(void* const* d_in, const int* in_sizes, int n_in,
                              void* d_out, int out_size)
{
    const float* s0 = (const float*)d_in[0];
    const float* s1 = (const float*)d_in[1];
    const float* s2 = (const float*)d_in[2];
    const float* s3 = (const float*)d_in[3];
    const float* W0 = (const float*)d_in[4];
    const float* b0 = (const float*)d_in[5];
    const float* W1 = (const float*)d_in[6];
    const float* W2 = (const float*)d_in[7];
    const float* b2 = (const float*)d_in[8];
    const float* W3 = (const float*)d_in[9];
    const float* W4 = (const float*)d_in[10];
    const float* b4 = (const float*)d_in[11];

    static_assert(SMEM_BYTES <= 227 * 1024, "smem budget");
    cudaFuncSetAttribute(step_kernel, cudaFuncAttributeMaxDynamicSharedMemorySize, SMEM_BYTES);
    cudaFuncSetAttribute(top_kernel,  cudaFuncAttributeMaxDynamicSharedMemorySize, SMEM_BYTES);

    wconv_kernel<<<dim3(DIM * DIM / 8 / 256, 5), 256>>>(W0, W1, W2, W3, W4);
    init_kernel<<<dim3(BD / 8 / 256, 4), 256>>>(s0, s1, s2, s3);

    top_kernel<<<32, 512, SMEM_BYTES>>>();

    for (int t = 0; t < NSTEPS; t++)
        step_kernel<<<128, 512, SMEM_BYTES>>>(t & 1, b0, b2, b4);

    out_kernel<<<BD / 256, 256>>>((float*)d_out);
}